// round 9
// baseline (speedup 1.0000x reference)
#include <cuda_runtime.h>
#include <cuda_bf16.h>
#include <mma.h>
#include <cstdint>

using namespace nvcuda;

#define NB    2
#define DIM   256
#define RES   256
#define FWS   8
#define HEADS 8
#define HD    32
#define NPX   64        // FWS*FWS
#define NWIN  512       // NB * 16 * 16
#define SCALE 0.17677669529663687f

// ---- scratch (device globals; no allocation) ----
__device__ float g_ll   [NWIN * DIM * NPX];
__device__ float g_lh   [NWIN * DIM * NPX];
__device__ float g_hl   [NWIN * DIM * NPX];
__device__ float g_hh   [NWIN * DIM * NPX];
__device__ float g_llout[NWIN * DIM * NPX];            // proj WITHOUT bias (bias folded into k_iwt)
__device__ float g_attn [NWIN * HEADS * NPX * NPX];    // [win][head][n][m]
__device__ __nv_bfloat16 g_xhi[NWIN * DIM * NPX];      // [win][c][px] relu'd, hi part
__device__ __nv_bfloat16 g_xlo[NWIN * DIM * NPX];      // lo part
__device__ __nv_bfloat16 g_whi[DIM * DIM];             // [oc][k]
__device__ __nv_bfloat16 g_wlo[DIM * DIM];

__device__ __forceinline__ void ffma2(uint64_t& acc, uint64_t a, uint64_t b) {
    asm("fma.rn.f32x2 %0, %1, %2, %0;" : "+l"(acc) : "l"(a), "l"(b));
}
__device__ __forceinline__ float hsum2(uint64_t v) {
    float lo, hi;
    asm("mov.b64 {%0,%1}, %2;" : "=f"(lo), "=f"(hi) : "l"(v));
    return lo + hi;
}

// ============================================================
// K0: split projection weights into bf16 hi/lo
// ============================================================
__global__ void k_wsplit(const float* __restrict__ pw) {
    int tid = blockIdx.x * blockDim.x + threadIdx.x;   // over 65536
    float w = pw[tid];
    __nv_bfloat16 hi = __float2bfloat16(w);
    float lo = w - __bfloat162float(hi);
    g_whi[tid] = hi;
    g_wlo[tid] = __float2bfloat16(lo);
}

// ============================================================
// K1: forward wavelet -> windowed layout. 2 horizontal px per thread (float4 loads)
// ============================================================
__global__ void k_fwt(const float* __restrict__ x, const float* __restrict__ wt) {
    int tid = blockIdx.x * blockDim.x + threadIdx.x;   // over NWIN*DIM*32
    int p   = tid & 31;            // r*4 + c2
    int ch  = (tid >> 5) & 255;
    int win = tid >> 13;
    int b   = win >> 8;
    int wy  = (win >> 4) & 15;
    int wx  = win & 15;
    int r = p >> 2, c2 = p & 3;
    int Y = (wy * 8 + r) * 2;
    int X = (wx * 8 + c2 * 2) * 2;
    const float* xb = x + (((size_t)(b * DIM + ch) * RES + Y) * RES + X);
    float4 a0 = *(const float4*)xb;
    float4 a1 = *(const float4*)(xb + RES);
    const float* w = wt + ch * 16;   // [s][dy][dx]
    int obase = (win * DIM + ch) * NPX + r * 8 + c2 * 2;
    #pragma unroll
    for (int s = 0; s < 4; s++) {
        float w0 = w[4*s], w1 = w[4*s+1], w2 = w[4*s+2], w3 = w[4*s+3];
        float v0 = a0.x*w0 + a0.y*w1 + a1.x*w2 + a1.y*w3;
        float v1 = a0.z*w0 + a0.w*w1 + a1.z*w2 + a1.w*w3;
        float2 vv = make_float2(v0, v1);
        float* dst = (s == 0) ? g_ll : (s == 1) ? g_lh : (s == 2) ? g_hl : g_hh;
        *(float2*)(dst + obase) = vv;
    }
}

// ============================================================
// K2a: attention matrices, one block per (window, head)
// ============================================================
#define KQ_STRIDE 36   // 16B-aligned rows, conflict-free (36 mod 32 = 4)

__global__ void __launch_bounds__(256) k_attnmat(
    const float* __restrict__ dww, const float* __restrict__ dwb,
    const float* __restrict__ ab,  const int* __restrict__ bidx)
{
    __shared__ __align__(16) float s_lh[HD * 66];
    __shared__ __align__(16) float s_k [NPX * KQ_STRIDE];
    __shared__ __align__(16) float s_q [NPX * KQ_STRIDE];

    const int t = threadIdx.x;
    const int bw = blockIdx.x;
    const int win = bw >> 3, h = bw & 7;
    const size_t base = (size_t)win * DIM * NPX + h * HD * NPX;
    const float* lsrc = g_lh + base;
    const float* ksrc = g_hl + base;
    #pragma unroll
    for (int i = 0; i < 8; i++) {
        int idx = t + 256 * i;
        int d = idx >> 6, m = idx & 63;
        s_lh[d * 66 + m] = lsrc[idx];
        s_k [m * KQ_STRIDE + d] = ksrc[idx];
    }
    __syncthreads();

    // q = depthwise 5x5 conv (zero pad outside window) + bias
    {
        int d = t >> 3, r = t & 7;
        const float* wq = dww + (h * HD + d) * 25;
        float wreg[25];
        #pragma unroll
        for (int i = 0; i < 25; i++) wreg[i] = wq[i];
        float bq = dwb[h * HD + d];
        const float* lr = s_lh + d * 66;
        #pragma unroll
        for (int c = 0; c < 8; c++) {
            float acc = bq;
            #pragma unroll
            for (int u = 0; u < 5; u++) {
                int rr = r + u - 2;
                if (rr < 0 || rr > 7) continue;
                #pragma unroll
                for (int v = 0; v < 5; v++) {
                    int cc = c + v - 2;
                    if (cc < 0 || cc > 7) continue;
                    acc += lr[rr * 8 + cc] * wreg[u * 5 + v];
                }
            }
            s_q[(r * 8 + c) * KQ_STRIDE + d] = acc;
        }
    }
    __syncthreads();

    // logits + softmax: thread (n = t>>2, q = t&3), m = q + 4*mm (bank-conflict-free)
    {
        int n = t >> 2, q = t & 3;
        ulonglong2 q4[8];
        const float* qrow = s_q + n * KQ_STRIDE;
        #pragma unroll
        for (int i = 0; i < 8; i++) q4[i] = *(const ulonglong2*)(qrow + 4 * i);
        const int* brow = bidx + n * 64;
        const float* abh = ab + h * 64;
        float logits[16];
        #pragma unroll
        for (int mm = 0; mm < 16; mm++) {
            int m = q + 4 * mm;
            const float* krow = s_k + m * KQ_STRIDE;
            uint64_t accA = 0ull, accB = 0ull;
            #pragma unroll
            for (int i = 0; i < 8; i++) {
                ulonglong2 k4 = *(const ulonglong2*)(krow + 4 * i);
                ffma2(accA, q4[i].x, k4.x);
                ffma2(accB, q4[i].y, k4.y);
            }
            logits[mm] = (hsum2(accA) + hsum2(accB)) * SCALE + abh[brow[m]];
        }
        float mx = logits[0];
        #pragma unroll
        for (int i = 1; i < 16; i++) mx = fmaxf(mx, logits[i]);
        mx = fmaxf(mx, __shfl_xor_sync(0xffffffffu, mx, 1));
        mx = fmaxf(mx, __shfl_xor_sync(0xffffffffu, mx, 2));
        float sum = 0.f;
        #pragma unroll
        for (int i = 0; i < 16; i++) { logits[i] = __expf(logits[i] - mx); sum += logits[i]; }
        sum += __shfl_xor_sync(0xffffffffu, sum, 1);
        sum += __shfl_xor_sync(0xffffffffu, sum, 2);
        float inv = 1.0f / sum;
        float* arow = g_attn + ((size_t)bw * 64 + n) * 64;
        #pragma unroll
        for (int mm = 0; mm < 16; mm++) arow[q + 4 * mm] = logits[mm] * inv;
    }
}

// ============================================================
// K2b: head recurrence. d-slices are independent: one CTA per
// (window, 16-d half) -> 1024 CTAs (6.9/SM, ~55 warps/SM).
// Thread = (d, 4 n's). Emits bf16 hi/lo splits.
// ============================================================
#define VA_STRIDE 68   // 16B-aligned; banks: stride mod 32 = 4

__global__ void __launch_bounds__(256) k_vrec() {
    __shared__ __align__(16) float s_v[16 * VA_STRIDE];
    __shared__ __align__(16) float s_a[NPX * VA_STRIDE];

    const int t = threadIdx.x;
    const int win  = blockIdx.x >> 1;
    const int dh   = blockIdx.x & 1;          // which 16-d half
    const size_t wbase = (size_t)win * DIM * NPX;
    const int d = t >> 4;                     // 0..15 local d
    const int j = t & 15;                     // n = j + 16*i, i<4

    // v0 = ll head 0, this half's d rows (16 rows x 64 = 256 float4)
    {
        const float4* vsrc = (const float4*)(g_ll + wbase + dh * 16 * NPX);
        int row = t >> 4, c4 = t & 15;
        *(float4*)(&s_v[row * VA_STRIDE + c4 * 4]) = vsrc[t];
    }

    for (int h = 0; h < HEADS; h++) {
        if (h > 0) __syncthreads();   // prior round's s_a reads done before overwrite
        // stage attn tile for this head (1024 float4)
        {
            const float4* asrc = (const float4*)(g_attn + ((size_t)(win * 8 + h)) * 4096);
            #pragma unroll
            for (int i = 0; i < 4; i++) {
                int flat = t + 256 * i;
                int row = flat >> 4, c4 = flat & 15;
                *(float4*)(&s_a[row * VA_STRIDE + c4 * 4]) = asrc[flat];
            }
        }
        __syncthreads();

        uint64_t accA[4], accB[4];
        #pragma unroll
        for (int i = 0; i < 4; i++) { accA[i] = 0ull; accB[i] = 0ull; }
        const float* vrow = s_v + d * VA_STRIDE;
        const float* ajb  = s_a + j * VA_STRIDE;
        #pragma unroll 4
        for (int m4 = 0; m4 < 16; m4++) {
            ulonglong2 vv = *(const ulonglong2*)(vrow + 4 * m4);
            #pragma unroll
            for (int i = 0; i < 4; i++) {
                ulonglong2 aa = *(const ulonglong2*)(ajb + (16 * i) * VA_STRIDE + 4 * m4);
                ffma2(accA[i], vv.x, aa.x);
                ffma2(accB[i], vv.y, aa.y);
            }
        }
        __syncthreads();   // all reads of s_v done before overwrite

        const int gd = h * HD + dh * 16 + d;            // global channel for output
        __nv_bfloat16* xh = g_xhi + wbase + gd * NPX;
        __nv_bfloat16* xl = g_xlo + wbase + gd * NPX;
        const float* nsrc = g_ll + wbase + ((h + 1) * HD + dh * 16 + d) * NPX;
        #pragma unroll
        for (int i = 0; i < 4; i++) {
            float o = hsum2(accA[i]) + hsum2(accB[i]);
            int nn = 16 * i + j;
            float ro = fmaxf(o, 0.f);
            __nv_bfloat16 hb = __float2bfloat16(ro);
            xh[nn] = hb;
            xl[nn] = __float2bfloat16(ro - __bfloat162float(hb));
            if (h < 7) s_v[d * VA_STRIDE + nn] = o + nsrc[nn];
        }
    }
}

// ============================================================
// K2c: 256x256 projection on tensor cores (bf16 WMMA, 3-term hi/lo split).
// ============================================================
#define XLD 72
#define PROJ_SMEM (2 * DIM * XLD * 2)   // hi+lo, bf16 -> 73,728 B

__global__ void __launch_bounds__(256, 2) k_proj() {
    extern __shared__ __nv_bfloat16 sx[];
    __nv_bfloat16* s_hi = sx;              // [256][72]
    __nv_bfloat16* s_lo = sx + DIM * XLD;  // [256][72]

    const int t = threadIdx.x;
    const int win = blockIdx.x;
    const size_t xbase = (size_t)win * DIM * NPX;

    {
        const uint4* shi = (const uint4*)(g_xhi + xbase);
        const uint4* slo = (const uint4*)(g_xlo + xbase);
        #pragma unroll
        for (int i = 0; i < 8; i++) {
            int flat = t + 256 * i;
            int row = flat >> 3, col = (flat & 7) * 8;
            *(uint4*)(s_hi + row * XLD + col) = shi[flat];
            *(uint4*)(s_lo + row * XLD + col) = slo[flat];
        }
    }
    __syncthreads();

    const int wid = t >> 5;
    const int ocb = wid * 32;

    wmma::fragment<wmma::accumulator, 16, 16, 16, float> c[2][4];
    #pragma unroll
    for (int mi = 0; mi < 2; mi++)
        #pragma unroll
        for (int ni = 0; ni < 4; ni++)
            wmma::fill_fragment(c[mi][ni], 0.0f);

    for (int kt = 0; kt < 16; kt++) {
        wmma::fragment<wmma::matrix_a, 16, 16, 16, __nv_bfloat16, wmma::row_major> ahi[2], alo[2];
        #pragma unroll
        for (int mi = 0; mi < 2; mi++) {
            wmma::load_matrix_sync(ahi[mi], g_whi + (ocb + mi * 16) * 256 + kt * 16, 256);
            wmma::load_matrix_sync(alo[mi], g_wlo + (ocb + mi * 16) * 256 + kt * 16, 256);
        }
        #pragma unroll
        for (int ni = 0; ni < 4; ni++) {
            wmma::fragment<wmma::matrix_b, 16, 16, 16, __nv_bfloat16, wmma::row_major> bhi, blo;
            wmma::load_matrix_sync(bhi, s_hi + (kt * 16) * XLD + ni * 16, XLD);
            wmma::load_matrix_sync(blo, s_lo + (kt * 16) * XLD + ni * 16, XLD);
            #pragma unroll
            for (int mi = 0; mi < 2; mi++) {
                wmma::mma_sync(c[mi][ni], ahi[mi], bhi, c[mi][ni]);
                wmma::mma_sync(c[mi][ni], ahi[mi], blo, c[mi][ni]);
                wmma::mma_sync(c[mi][ni], alo[mi], bhi, c[mi][ni]);
            }
        }
    }

    float* dst = g_llout + xbase;
    #pragma unroll
    for (int mi = 0; mi < 2; mi++)
        #pragma unroll
        for (int ni = 0; ni < 4; ni++)
            wmma::store_matrix_sync(dst + (ocb + mi * 16) * NPX + ni * 16,
                                    c[mi][ni], NPX, wmma::mem_row_major);
}

// ============================================================
// K3: inverse wavelet; projection bias pb[ch] folded in here
// ============================================================
__global__ void k_iwt(const float* __restrict__ iwt, const float* __restrict__ pb,
                      float* __restrict__ out) {
    int tid = blockIdx.x * blockDim.x + threadIdx.x;   // over NB*DIM*RES*RES
    int X  = tid & 255;
    int Y  = (tid >> 8) & 255;
    int ch = (tid >> 16) & 255;
    int b  = tid >> 24;
    int y = Y >> 1, x = X >> 1;
    int win = (b * 16 + (y >> 3)) * 16 + (x >> 3);
    int px  = (y & 7) * 8 + (x & 7);
    int base = (win * DIM + ch) * NPX + px;
    const float* w = iwt + ch * 16 + (Y & 1) * 2 + (X & 1);
    float ll = g_llout[base] + pb[ch];
    float v = ll * w[0] + g_lh[base] * w[4]
            + g_hl[base] * w[8] + g_hh[base] * w[12];
    out[tid] = v;
}

// ============================================================
extern "C" void kernel_launch(void* const* d_in, const int* in_sizes, int n_in,
                              void* d_out, int out_size) {
    const float* x   = (const float*)d_in[0];
    const float* wt  = (const float*)d_in[1];
    const float* iwt = (const float*)d_in[2];
    const float* dww = (const float*)d_in[3];
    const float* dwb = (const float*)d_in[4];
    const float* pw  = (const float*)d_in[5];
    const float* pb  = (const float*)d_in[6];
    const float* ab  = (const float*)d_in[7];
    const int*   bidx= (const int*)d_in[8];
    float* out = (float*)d_out;

    (void)in_sizes; (void)n_in; (void)out_size;

    cudaFuncSetAttribute(k_proj, cudaFuncAttributeMaxDynamicSharedMemorySize, PROJ_SMEM);

    k_wsplit <<<DIM * DIM / 256, 256>>>(pw);
    k_fwt    <<<(NWIN * DIM * 32) / 256, 256>>>(x, wt);
    k_attnmat<<<NWIN * HEADS, 256>>>(dww, dwb, ab, bidx);
    k_vrec   <<<NWIN * 2, 256>>>();
    k_proj   <<<NWIN, 256, PROJ_SMEM>>>();
    k_iwt    <<<(NB * DIM * RES * RES) / 256, 256>>>(iwt, pb, out);
}

// round 10
// speedup vs baseline: 1.3791x; 1.3791x over previous
#include <cuda_runtime.h>
#include <cuda_bf16.h>
#include <mma.h>
#include <cstdint>

using namespace nvcuda;

#define NB    2
#define DIM   256
#define RES   256
#define FWS   8
#define HEADS 8
#define HD    32
#define NPX   64        // FWS*FWS
#define NWIN  512       // NB * 16 * 16
#define SCALE 0.17677669529663687f

// ---- scratch (device globals; no allocation) ----
__device__ float g_ll   [NWIN * DIM * NPX];
__device__ float g_lh   [NWIN * DIM * NPX];
__device__ float g_hl   [NWIN * DIM * NPX];
__device__ float g_hh   [NWIN * DIM * NPX];
__device__ float g_llout[NWIN * DIM * NPX];            // proj WITHOUT bias (bias folded into k_iwt)
__device__ __nv_bfloat16 g_ahi[NWIN * HEADS * NPX * NPX];  // attn probs hi  [win][h][n][m]
__device__ __nv_bfloat16 g_alo[NWIN * HEADS * NPX * NPX];  // attn probs lo
__device__ __nv_bfloat16 g_xhi[NWIN * DIM * NPX];      // [win][c][px] relu'd, hi part
__device__ __nv_bfloat16 g_xlo[NWIN * DIM * NPX];      // lo part
__device__ __nv_bfloat16 g_whi[DIM * DIM];             // [oc][k]
__device__ __nv_bfloat16 g_wlo[DIM * DIM];

__device__ __forceinline__ void ffma2(uint64_t& acc, uint64_t a, uint64_t b) {
    asm("fma.rn.f32x2 %0, %1, %2, %0;" : "+l"(acc) : "l"(a), "l"(b));
}
__device__ __forceinline__ float hsum2(uint64_t v) {
    float lo, hi;
    asm("mov.b64 {%0,%1}, %2;" : "=f"(lo), "=f"(hi) : "l"(v));
    return lo + hi;
}

// ============================================================
// K0: split projection weights into bf16 hi/lo
// ============================================================
__global__ void k_wsplit(const float* __restrict__ pw) {
    int tid = blockIdx.x * blockDim.x + threadIdx.x;   // over 65536
    float w = pw[tid];
    __nv_bfloat16 hi = __float2bfloat16(w);
    float lo = w - __bfloat162float(hi);
    g_whi[tid] = hi;
    g_wlo[tid] = __float2bfloat16(lo);
}

// ============================================================
// K1: forward wavelet -> windowed layout. 2 horizontal px per thread (float4 loads)
// ============================================================
__global__ void k_fwt(const float* __restrict__ x, const float* __restrict__ wt) {
    int tid = blockIdx.x * blockDim.x + threadIdx.x;   // over NWIN*DIM*32
    int p   = tid & 31;            // r*4 + c2
    int ch  = (tid >> 5) & 255;
    int win = tid >> 13;
    int b   = win >> 8;
    int wy  = (win >> 4) & 15;
    int wx  = win & 15;
    int r = p >> 2, c2 = p & 3;
    int Y = (wy * 8 + r) * 2;
    int X = (wx * 8 + c2 * 2) * 2;
    const float* xb = x + (((size_t)(b * DIM + ch) * RES + Y) * RES + X);
    float4 a0 = *(const float4*)xb;
    float4 a1 = *(const float4*)(xb + RES);
    const float* w = wt + ch * 16;   // [s][dy][dx]
    int obase = (win * DIM + ch) * NPX + r * 8 + c2 * 2;
    #pragma unroll
    for (int s = 0; s < 4; s++) {
        float w0 = w[4*s], w1 = w[4*s+1], w2 = w[4*s+2], w3 = w[4*s+3];
        float v0 = a0.x*w0 + a0.y*w1 + a1.x*w2 + a1.y*w3;
        float v1 = a0.z*w0 + a0.w*w1 + a1.z*w2 + a1.w*w3;
        float2 vv = make_float2(v0, v1);
        float* dst = (s == 0) ? g_ll : (s == 1) ? g_lh : (s == 2) ? g_hl : g_hh;
        *(float2*)(dst + obase) = vv;
    }
}

// ============================================================
// K2a: attention matrices, one block per (window, head).
// Emits probs as bf16 hi/lo for the WMMA V-path.
// ============================================================
#define KQ_STRIDE 36   // 16B-aligned rows, conflict-free (36 mod 32 = 4)

__global__ void __launch_bounds__(256) k_attnmat(
    const float* __restrict__ dww, const float* __restrict__ dwb,
    const float* __restrict__ ab,  const int* __restrict__ bidx)
{
    __shared__ __align__(16) float s_lh[HD * 66];
    __shared__ __align__(16) float s_k [NPX * KQ_STRIDE];
    __shared__ __align__(16) float s_q [NPX * KQ_STRIDE];

    const int t = threadIdx.x;
    const int bw = blockIdx.x;
    const int win = bw >> 3, h = bw & 7;
    const size_t base = (size_t)win * DIM * NPX + h * HD * NPX;
    const float* lsrc = g_lh + base;
    const float* ksrc = g_hl + base;
    #pragma unroll
    for (int i = 0; i < 8; i++) {
        int idx = t + 256 * i;
        int d = idx >> 6, m = idx & 63;
        s_lh[d * 66 + m] = lsrc[idx];
        s_k [m * KQ_STRIDE + d] = ksrc[idx];
    }
    __syncthreads();

    // q = depthwise 5x5 conv (zero pad outside window) + bias
    {
        int d = t >> 3, r = t & 7;
        const float* wq = dww + (h * HD + d) * 25;
        float wreg[25];
        #pragma unroll
        for (int i = 0; i < 25; i++) wreg[i] = wq[i];
        float bq = dwb[h * HD + d];
        const float* lr = s_lh + d * 66;
        #pragma unroll
        for (int c = 0; c < 8; c++) {
            float acc = bq;
            #pragma unroll
            for (int u = 0; u < 5; u++) {
                int rr = r + u - 2;
                if (rr < 0 || rr > 7) continue;
                #pragma unroll
                for (int v = 0; v < 5; v++) {
                    int cc = c + v - 2;
                    if (cc < 0 || cc > 7) continue;
                    acc += lr[rr * 8 + cc] * wreg[u * 5 + v];
                }
            }
            s_q[(r * 8 + c) * KQ_STRIDE + d] = acc;
        }
    }
    __syncthreads();

    // logits + softmax: thread (n = t>>2, q = t&3), m = q + 4*mm (bank-conflict-free)
    {
        int n = t >> 2, q = t & 3;
        ulonglong2 q4[8];
        const float* qrow = s_q + n * KQ_STRIDE;
        #pragma unroll
        for (int i = 0; i < 8; i++) q4[i] = *(const ulonglong2*)(qrow + 4 * i);
        const int* brow = bidx + n * 64;
        const float* abh = ab + h * 64;
        float logits[16];
        #pragma unroll
        for (int mm = 0; mm < 16; mm++) {
            int m = q + 4 * mm;
            const float* krow = s_k + m * KQ_STRIDE;
            uint64_t accA = 0ull, accB = 0ull;
            #pragma unroll
            for (int i = 0; i < 8; i++) {
                ulonglong2 k4 = *(const ulonglong2*)(krow + 4 * i);
                ffma2(accA, q4[i].x, k4.x);
                ffma2(accB, q4[i].y, k4.y);
            }
            logits[mm] = (hsum2(accA) + hsum2(accB)) * SCALE + abh[brow[m]];
        }
        float mx = logits[0];
        #pragma unroll
        for (int i = 1; i < 16; i++) mx = fmaxf(mx, logits[i]);
        mx = fmaxf(mx, __shfl_xor_sync(0xffffffffu, mx, 1));
        mx = fmaxf(mx, __shfl_xor_sync(0xffffffffu, mx, 2));
        float sum = 0.f;
        #pragma unroll
        for (int i = 0; i < 16; i++) { logits[i] = __expf(logits[i] - mx); sum += logits[i]; }
        sum += __shfl_xor_sync(0xffffffffu, sum, 1);
        sum += __shfl_xor_sync(0xffffffffu, sum, 2);
        float inv = 1.0f / sum;
        __nv_bfloat16* ah = g_ahi + ((size_t)bw * 64 + n) * 64;
        __nv_bfloat16* al = g_alo + ((size_t)bw * 64 + n) * 64;
        #pragma unroll
        for (int mm = 0; mm < 16; mm++) {
            float p = logits[mm] * inv;
            __nv_bfloat16 hb = __float2bfloat16(p);
            ah[q + 4 * mm] = hb;
            al[q + 4 * mm] = __float2bfloat16(p - __bfloat162float(hb));
        }
    }
}

// ============================================================
// K2b: head recurrence on tensor cores. One CTA per window, 8 warps.
// out(32x64) = v(32x64) . attn^T : warp (mi,ni) owns 16x16 C tile.
// bf16 hi/lo 3-term split on both operands, fp32 accum.
// ============================================================
#define AS 72    // bf16 row stride for attn/v tiles in smem
#define CS 68    // fp32 row stride for C staging

__global__ void __launch_bounds__(256) k_vrec() {
    __shared__ __align__(16) __nv_bfloat16 s_ahi[NPX * AS];
    __shared__ __align__(16) __nv_bfloat16 s_alo[NPX * AS];
    __shared__ __align__(16) __nv_bfloat16 s_vhi[HD * AS];
    __shared__ __align__(16) __nv_bfloat16 s_vlo[HD * AS];
    __shared__ __align__(16) float s_c[HD * CS];

    const int t = threadIdx.x;
    const int win = blockIdx.x;
    const size_t wbase = (size_t)win * DIM * NPX;
    const int wid = t >> 5;
    const int mi = wid >> 2;       // 0..1 : d block
    const int ni = wid & 3;        // 0..3 : n block

    // v0 = ll head 0, split to bf16 hi/lo
    #pragma unroll
    for (int i = 0; i < 8; i++) {
        int flat = t + 256 * i;            // 2048
        int d = flat >> 6, n = flat & 63;
        float v = g_ll[wbase + flat];
        __nv_bfloat16 hb = __float2bfloat16(v);
        s_vhi[d * AS + n] = hb;
        s_vlo[d * AS + n] = __float2bfloat16(v - __bfloat162float(hb));
    }

    for (int h = 0; h < HEADS; h++) {
        // stage attn hi/lo tiles for this head (512 uint4 each)
        {
            const uint4* ah = (const uint4*)(g_ahi + ((size_t)(win * 8 + h)) * 4096);
            const uint4* al = (const uint4*)(g_alo + ((size_t)(win * 8 + h)) * 4096);
            #pragma unroll
            for (int i = 0; i < 2; i++) {
                int flat = t + 256 * i;
                int row = flat >> 3, col = (flat & 7) * 8;
                *(uint4*)(s_ahi + row * AS + col) = ah[flat];
                *(uint4*)(s_alo + row * AS + col) = al[flat];
            }
        }
        __syncthreads();   // a staged; v from prior epilogue visible

        wmma::fragment<wmma::accumulator, 16, 16, 16, float> c;
        wmma::fill_fragment(c, 0.0f);
        #pragma unroll
        for (int k = 0; k < 4; k++) {
            wmma::fragment<wmma::matrix_a, 16, 16, 16, __nv_bfloat16, wmma::row_major> vh, vl;
            wmma::fragment<wmma::matrix_b, 16, 16, 16, __nv_bfloat16, wmma::col_major> bh, bl;
            wmma::load_matrix_sync(vh, s_vhi + mi * 16 * AS + k * 16, AS);
            wmma::load_matrix_sync(vl, s_vlo + mi * 16 * AS + k * 16, AS);
            wmma::load_matrix_sync(bh, s_ahi + ni * 16 * AS + k * 16, AS);
            wmma::load_matrix_sync(bl, s_alo + ni * 16 * AS + k * 16, AS);
            wmma::mma_sync(c, vh, bh, c);
            wmma::mma_sync(c, vh, bl, c);
            wmma::mma_sync(c, vl, bh, c);
        }
        wmma::store_matrix_sync(s_c + mi * 16 * CS + ni * 16, c, CS, wmma::mem_row_major);
        __syncthreads();   // C ready; all reads of s_a/s_v done

        // epilogue: emit X split, update v split (pre-relu recurrence)
        const float* nsrc = g_ll + wbase + (h + 1) * HD * NPX;
        #pragma unroll
        for (int i = 0; i < 8; i++) {
            int flat = t + 256 * i;
            int d = flat >> 6, n = flat & 63;
            float o = s_c[d * CS + n];
            float ro = fmaxf(o, 0.f);
            __nv_bfloat16 hb = __float2bfloat16(ro);
            g_xhi[wbase + h * HD * NPX + flat] = hb;
            g_xlo[wbase + h * HD * NPX + flat] = __float2bfloat16(ro - __bfloat162float(hb));
            if (h < 7) {
                float vn = o + nsrc[flat];
                __nv_bfloat16 vhb = __float2bfloat16(vn);
                s_vhi[d * AS + n] = vhb;
                s_vlo[d * AS + n] = __float2bfloat16(vn - __bfloat162float(vhb));
            }
        }
        __syncthreads();   // v updated before next head's MMA; s_c reads done
    }
}

// ============================================================
// K2c: 256x256 projection on tensor cores (bf16 WMMA, 3-term hi/lo split).
// ============================================================
#define XLD 72
#define PROJ_SMEM (2 * DIM * XLD * 2)   // hi+lo, bf16 -> 73,728 B

__global__ void __launch_bounds__(256, 2) k_proj() {
    extern __shared__ __nv_bfloat16 sx[];
    __nv_bfloat16* s_hi = sx;              // [256][72]
    __nv_bfloat16* s_lo = sx + DIM * XLD;  // [256][72]

    const int t = threadIdx.x;
    const int win = blockIdx.x;
    const size_t xbase = (size_t)win * DIM * NPX;

    {
        const uint4* shi = (const uint4*)(g_xhi + xbase);
        const uint4* slo = (const uint4*)(g_xlo + xbase);
        #pragma unroll
        for (int i = 0; i < 8; i++) {
            int flat = t + 256 * i;
            int row = flat >> 3, col = (flat & 7) * 8;
            *(uint4*)(s_hi + row * XLD + col) = shi[flat];
            *(uint4*)(s_lo + row * XLD + col) = slo[flat];
        }
    }
    __syncthreads();

    const int wid = t >> 5;
    const int ocb = wid * 32;

    wmma::fragment<wmma::accumulator, 16, 16, 16, float> c[2][4];
    #pragma unroll
    for (int mi = 0; mi < 2; mi++)
        #pragma unroll
        for (int ni = 0; ni < 4; ni++)
            wmma::fill_fragment(c[mi][ni], 0.0f);

    for (int kt = 0; kt < 16; kt++) {
        wmma::fragment<wmma::matrix_a, 16, 16, 16, __nv_bfloat16, wmma::row_major> ahi[2], alo[2];
        #pragma unroll
        for (int mi = 0; mi < 2; mi++) {
            wmma::load_matrix_sync(ahi[mi], g_whi + (ocb + mi * 16) * 256 + kt * 16, 256);
            wmma::load_matrix_sync(alo[mi], g_wlo + (ocb + mi * 16) * 256 + kt * 16, 256);
        }
        #pragma unroll
        for (int ni = 0; ni < 4; ni++) {
            wmma::fragment<wmma::matrix_b, 16, 16, 16, __nv_bfloat16, wmma::row_major> bhi, blo;
            wmma::load_matrix_sync(bhi, s_hi + (kt * 16) * XLD + ni * 16, XLD);
            wmma::load_matrix_sync(blo, s_lo + (kt * 16) * XLD + ni * 16, XLD);
            #pragma unroll
            for (int mi = 0; mi < 2; mi++) {
                wmma::mma_sync(c[mi][ni], ahi[mi], bhi, c[mi][ni]);
                wmma::mma_sync(c[mi][ni], ahi[mi], blo, c[mi][ni]);
                wmma::mma_sync(c[mi][ni], alo[mi], bhi, c[mi][ni]);
            }
        }
    }

    float* dst = g_llout + xbase;
    #pragma unroll
    for (int mi = 0; mi < 2; mi++)
        #pragma unroll
        for (int ni = 0; ni < 4; ni++)
            wmma::store_matrix_sync(dst + (ocb + mi * 16) * NPX + ni * 16,
                                    c[mi][ni], NPX, wmma::mem_row_major);
}

// ============================================================
// K3: inverse wavelet; projection bias pb[ch] folded in here
// ============================================================
__global__ void k_iwt(const float* __restrict__ iwt, const float* __restrict__ pb,
                      float* __restrict__ out) {
    int tid = blockIdx.x * blockDim.x + threadIdx.x;   // over NB*DIM*RES*RES
    int X  = tid & 255;
    int Y  = (tid >> 8) & 255;
    int ch = (tid >> 16) & 255;
    int b  = tid >> 24;
    int y = Y >> 1, x = X >> 1;
    int win = (b * 16 + (y >> 3)) * 16 + (x >> 3);
    int px  = (y & 7) * 8 + (x & 7);
    int base = (win * DIM + ch) * NPX + px;
    const float* w = iwt + ch * 16 + (Y & 1) * 2 + (X & 1);
    float ll = g_llout[base] + pb[ch];
    float v = ll * w[0] + g_lh[base] * w[4]
            + g_hl[base] * w[8] + g_hh[base] * w[12];
    out[tid] = v;
}

// ============================================================
extern "C" void kernel_launch(void* const* d_in, const int* in_sizes, int n_in,
                              void* d_out, int out_size) {
    const float* x   = (const float*)d_in[0];
    const float* wt  = (const float*)d_in[1];
    const float* iwt = (const float*)d_in[2];
    const float* dww = (const float*)d_in[3];
    const float* dwb = (const float*)d_in[4];
    const float* pw  = (const float*)d_in[5];
    const float* pb  = (const float*)d_in[6];
    const float* ab  = (const float*)d_in[7];
    const int*   bidx= (const int*)d_in[8];
    float* out = (float*)d_out;

    (void)in_sizes; (void)n_in; (void)out_size;

    cudaFuncSetAttribute(k_proj, cudaFuncAttributeMaxDynamicSharedMemorySize, PROJ_SMEM);

    k_wsplit <<<DIM * DIM / 256, 256>>>(pw);
    k_fwt    <<<(NWIN * DIM * 32) / 256, 256>>>(x, wt);
    k_attnmat<<<NWIN * HEADS, 256>>>(dww, dwb, ab, bidx);
    k_vrec   <<<NWIN, 256>>>();
    k_proj   <<<NWIN, 256, PROJ_SMEM>>>();
    k_iwt    <<<(NB * DIM * RES * RES) / 256, 256>>>(iwt, pb, out);
}